// round 1
// baseline (speedup 1.0000x reference)
#include <cuda_runtime.h>

// Problem constants (fixed by the dataset)
static constexpr int S      = 8192;
static constexpr int CIN    = 32;
static constexpr int COUT   = 8;
static constexpr int BB     = 128;

static constexpr int STILE   = 16;               // s-positions per block
static constexpr int THREADS = 256;
static constexpr int BQ      = THREADS / STILE;  // 16 batch-groups
static constexpr int B_PER_PASS = BQ * 4;        // 64 batches per pass
static constexpr int NPASS   = BB / B_PER_PASS;  // 2

// tanh(x) = (e^{2x}-1)/(e^{2x}+1), e^{2x} via ex2.approx on 2x*log2(e).
// Clamp exponent to +-30: for |x|>10.4 tanh is 1 to within 2e-9 in fp32,
// and the clamp avoids inf/inf. rel err ~1e-6 overall.
__device__ __forceinline__ float fast_tanh(float v) {
    float z = fminf(fmaxf(v * 2.88539008177793f, -30.0f), 30.0f);
    float e;
    asm("ex2.approx.f32 %0, %1;" : "=f"(e) : "f"(z));
    return __fdividef(e - 1.0f, e + 1.0f);
}

__global__ __launch_bounds__(THREADS, 1)
void lc3_kernel(const float* __restrict__ x,
                const float* __restrict__ w1,
                const float* __restrict__ w2,
                const float* __restrict__ bias,
                float* __restrict__ out)
{
    __shared__ float sw1s[CIN * STILE];          // 2 KB
    __shared__ float w2s[COUT * CIN * STILE];    // 16 KB
    __shared__ float biass[COUT * STILE];        // 0.5 KB

    const int s0  = blockIdx.x * STILE;
    const int tid = threadIdx.x;
    constexpr int NV = STILE / 4;                // float4 per row

    // ---- Stage w2 tile into smem (float4, fully coalesced) ----
    for (int k = tid; k < COUT * CIN * NV; k += THREADS) {
        int row = k / NV, sv = k % NV;
        float4 v = *reinterpret_cast<const float4*>(w2 + (size_t)row * S + s0 + sv * 4);
        reinterpret_cast<float4*>(w2s)[k] = v;
    }
    // ---- sw1[j,s] = sum_i w1[i,j,s] (reads w1 slice exactly once) ----
    for (int k = tid; k < CIN * NV; k += THREADS) {
        int j = k / NV, sv = k % NV;
        const float* p = w1 + (size_t)j * S + s0 + sv * 4;
        float ax = 0.f, ay = 0.f, az = 0.f, aw = 0.f;
        #pragma unroll
        for (int i = 0; i < CIN; i++) {
            float4 v = *reinterpret_cast<const float4*>(p + (size_t)i * CIN * S);
            ax += v.x; ay += v.y; az += v.z; aw += v.w;
        }
        reinterpret_cast<float4*>(sw1s)[k] = make_float4(ax, ay, az, aw);
    }
    // ---- bias tile ----
    for (int k = tid; k < COUT * NV; k += THREADS) {
        int o = k / NV, sv = k % NV;
        reinterpret_cast<float4*>(biass)[k] =
            *reinterpret_cast<const float4*>(bias + (size_t)o * S + s0 + sv * 4);
    }
    __syncthreads();

    const int si = tid % STILE;   // s within tile
    const int bg = tid / STILE;   // batch group 0..15

    #pragma unroll
    for (int pass = 0; pass < NPASS; pass++) {
        const int b0 = pass * B_PER_PASS + bg * 4;
        float acc[4][COUT];
        #pragma unroll
        for (int bi = 0; bi < 4; bi++)
            #pragma unroll
            for (int o = 0; o < COUT; o++) acc[bi][o] = 0.f;

        const float* xp = x + (size_t)b0 * CIN * S + s0 + si;

        #pragma unroll 4
        for (int j = 0; j < CIN; j++) {
            float sw = sw1s[j * STILE + si];
            float h0 = fast_tanh(xp[(0 * CIN + j) * S] * sw);
            float h1 = fast_tanh(xp[(1 * CIN + j) * S] * sw);
            float h2 = fast_tanh(xp[(2 * CIN + j) * S] * sw);
            float h3 = fast_tanh(xp[(3 * CIN + j) * S] * sw);
            #pragma unroll
            for (int o = 0; o < COUT; o++) {
                float wv = w2s[(o * CIN + j) * STILE + si];
                acc[0][o] = fmaf(h0, wv, acc[0][o]);
                acc[1][o] = fmaf(h1, wv, acc[1][o]);
                acc[2][o] = fmaf(h2, wv, acc[2][o]);
                acc[3][o] = fmaf(h3, wv, acc[3][o]);
            }
        }

        #pragma unroll
        for (int bi = 0; bi < 4; bi++) {
            #pragma unroll
            for (int o = 0; o < COUT; o++) {
                out[((size_t)(b0 + bi) * COUT + o) * S + s0 + si] =
                    fast_tanh(acc[bi][o] + biass[o * STILE + si]);
            }
        }
    }
}

extern "C" void kernel_launch(void* const* d_in, const int* in_sizes, int n_in,
                              void* d_out, int out_size) {
    const float* x    = (const float*)d_in[0];   // (128, 32, 8192)
    const float* w1   = (const float*)d_in[1];   // (32, 32, 8192)
    const float* w2   = (const float*)d_in[2];   // (8, 32, 8192)
    const float* bias = (const float*)d_in[3];   // (8, 8192)
    float* out        = (float*)d_out;           // (128, 8, 8192)
    lc3_kernel<<<S / STILE, THREADS>>>(x, w1, w2, bias, out);
}

// round 3
// speedup vs baseline: 1.4061x; 1.4061x over previous
#include <cuda_runtime.h>

// Problem constants (fixed by the dataset)
static constexpr int S    = 8192;
static constexpr int CIN  = 32;
static constexpr int COUT = 8;
static constexpr int BB   = 128;

// Main kernel tiling
static constexpr int STILE   = 32;               // s-positions per block (one full warp width)
static constexpr int THREADS = 256;
static constexpr int NWARP   = THREADS / 32;     // 8 batch groups
static constexpr int BPT     = 2;                // batches per thread
static constexpr int B_PER_BLOCK = NWARP * BPT;  // 16
static constexpr int BSPLIT  = BB / B_PER_BLOCK; // 8 blocks share one s-tile

// Scratch for sw1[j,s] = sum_i w1[i,j,s]  (1 MB, __device__ global = allowed scratch)
__device__ float g_sw1[CIN * S];

// tanh(x) = (e^{2x}-1)/(e^{2x}+1); ex2.approx + fast divide; clamp avoids inf/inf.
__device__ __forceinline__ float fast_tanh(float v) {
    float z = fminf(fmaxf(v * 2.88539008177793f, -30.0f), 30.0f);
    float e;
    asm("ex2.approx.f32 %0, %1;" : "=f"(e) : "f"(z));
    return __fdividef(e - 1.0f, e + 1.0f);
}

// ---- Kernel 1: reduce w1 over i (reads w1 exactly once, fully coalesced) ----
__global__ __launch_bounds__(256)
void sw1_kernel(const float* __restrict__ w1) {
    // one thread per (j, 4-consecutive-s)
    int idx = blockIdx.x * 256 + threadIdx.x;          // 0 .. 32*2048-1
    int j  = idx / (S / 4);
    int s4 = idx % (S / 4);
    const float* p = w1 + (size_t)j * S + s4 * 4;
    float4 a = make_float4(0.f, 0.f, 0.f, 0.f);
    #pragma unroll
    for (int i = 0; i < CIN; i++) {
        float4 v = *reinterpret_cast<const float4*>(p + (size_t)i * CIN * S);
        a.x += v.x; a.y += v.y; a.z += v.z; a.w += v.w;
    }
    *reinterpret_cast<float4*>(g_sw1 + (size_t)j * S + s4 * 4) = a;
}

// ---- Kernel 2: fused tanh-scale + contraction + bias + tanh ----
__global__ __launch_bounds__(THREADS, 4)
void lc3_main(const float* __restrict__ x,
              const float* __restrict__ w2,
              const float* __restrict__ bias,
              float* __restrict__ out)
{
    __shared__ float w2s[COUT * CIN * STILE];   // 32 KB
    __shared__ float sw1s[CIN * STILE];         // 4 KB
    __shared__ float biass[COUT * STILE];       // 1 KB

    const int stile  = blockIdx.x >> 3;         // 0..255
    const int bsplit = blockIdx.x & (BSPLIT - 1);
    const int s0     = stile * STILE;
    const int tid    = threadIdx.x;
    constexpr int NV = STILE / 4;

    // Stage w2 tile (float4, coalesced; later blocks hit L2)
    for (int k = tid; k < COUT * CIN * NV; k += THREADS) {
        int row = k / NV, sv = k % NV;
        reinterpret_cast<float4*>(w2s)[k] =
            *reinterpret_cast<const float4*>(w2 + (size_t)row * S + s0 + sv * 4);
    }
    // Stage sw1 tile from scratch
    for (int k = tid; k < CIN * NV; k += THREADS) {
        int j = k / NV, sv = k % NV;
        reinterpret_cast<float4*>(sw1s)[k] =
            *reinterpret_cast<const float4*>(g_sw1 + (size_t)j * S + s0 + sv * 4);
    }
    // Stage bias tile
    for (int k = tid; k < COUT * NV; k += THREADS) {
        int o = k / NV, sv = k % NV;
        reinterpret_cast<float4*>(biass)[k] =
            *reinterpret_cast<const float4*>(bias + (size_t)o * S + s0 + sv * 4);
    }
    __syncthreads();

    const int si = tid & 31;          // s within tile == lane
    const int bg = tid >> 5;          // warp id = batch group
    const int b0 = bsplit * B_PER_BLOCK + bg * BPT;

    float acc0[COUT], acc1[COUT];
    #pragma unroll
    for (int o = 0; o < COUT; o++) { acc0[o] = 0.f; acc1[o] = 0.f; }

    const float* xp0 = x + (size_t)b0 * CIN * S + s0 + si;
    const float* xp1 = xp0 + (size_t)CIN * S;

    #pragma unroll 4
    for (int j = 0; j < CIN; j++) {
        // Issue both global loads before any MUFU work (MLP=2 per step)
        float v0 = xp0[(size_t)j * S];
        float v1 = xp1[(size_t)j * S];
        float sw = sw1s[j * STILE + si];
        float h0 = fast_tanh(v0 * sw);
        float h1 = fast_tanh(v1 * sw);
        #pragma unroll
        for (int o = 0; o < COUT; o++) {
            float wv = w2s[(o * CIN + j) * STILE + si];
            acc0[o] = fmaf(h0, wv, acc0[o]);
            acc1[o] = fmaf(h1, wv, acc1[o]);
        }
    }

    #pragma unroll
    for (int o = 0; o < COUT; o++) {
        float bv = biass[o * STILE + si];
        out[((size_t)(b0 + 0) * COUT + o) * S + s0 + si] = fast_tanh(acc0[o] + bv);
        out[((size_t)(b0 + 1) * COUT + o) * S + s0 + si] = fast_tanh(acc1[o] + bv);
    }
}

extern "C" void kernel_launch(void* const* d_in, const int* in_sizes, int n_in,
                              void* d_out, int out_size) {
    const float* x    = (const float*)d_in[0];   // (128, 32, 8192)
    const float* w1   = (const float*)d_in[1];   // (32, 32, 8192)
    const float* w2   = (const float*)d_in[2];   // (8, 32, 8192)
    const float* bias = (const float*)d_in[3];   // (8, 8192)
    float* out        = (float*)d_out;           // (128, 8, 8192)

    sw1_kernel<<<(CIN * S / 4) / 256, 256>>>(w1);
    lc3_main<<<(S / STILE) * BSPLIT, THREADS>>>(x, w2, bias, out);
}